// round 12
// baseline (speedup 1.0000x reference)
#include <cuda_runtime.h>
#include <cstdint>

// SheafConvLayer:
//   out[n,:] = relu( W_self[n] @ x[n] + b_self[n]
//                    + sum_{e: dst[e]==n} ( W_edge[e] @ x[src[e]] + b_edge[e] ) )
// D = 16.
//
// Inputs (metadata order):
//   0: x           f32 [N,16]
//   1: edge_index  int [2,E]  (int32 or int64, runtime-detected)
//   2: weight_edge f32 [E,16,16]
//   3: weight_self f32 [N,16,16]
//   4: bias_edge   f32 [E,16]
//   5: bias_self   f32 [N,16]
// out: f32 [N,16]
//
// R11: per-warp autonomous cp.async pipelines gave 6.6TB/s (DRAM 83%).
// R12 changes: (a) bias moved out of smem into prefetched registers ->
// stage = exactly 4KB -> 8KB/warp -> with 128-thread blocks, 7 CTAs/SM =
// 28 warps (was 24); (b) self term uses plain stores (covers every output
// element once) -> zero_kernel deleted; edge atomics accumulate on top.

#define D 16
#define EPW 4                        // edges per warp-tile
#define STAGE_BYTES (EPW * 1024)     // 4 KB weights per stage
#define NSTAGE 2
#define WARP_SMEM (NSTAGE * STAGE_BYTES)        // 8 KB
#define BLOCK_WARPS 4
#define BLOCK_THREADS (BLOCK_WARPS * 32)        // 128
#define SMEM_TOTAL (BLOCK_WARPS * WARP_SMEM)    // 32 KB

__device__ int g_idx_is64;

__device__ __forceinline__ float dot4(float4 a, float4 b) {
    return a.x * b.x + a.y * b.y + a.z * b.z + a.w * b.w;
}

__device__ __forceinline__ void red_add_v2(float* addr, float a, float b) {
    asm volatile("red.global.add.v2.f32 [%0], {%1, %2};"
                 :: "l"(addr), "f"(a), "f"(b) : "memory");
}

__device__ __forceinline__ uint32_t smem_u32(const void* p) {
    uint32_t a;
    asm("{ .reg .u64 t; cvta.to.shared.u64 t, %1; cvt.u32.u64 %0, t; }"
        : "=r"(a) : "l"(p));
    return a;
}

__device__ __forceinline__ void cp16(uint32_t dst, const void* src) {
    asm volatile("cp.async.cg.shared.global [%0], [%1], 16;"
                 :: "r"(dst), "l"(src) : "memory");
}

__device__ __forceinline__ void cp_commit() {
    asm volatile("cp.async.commit_group;" ::: "memory");
}

__device__ __forceinline__ void cp_wait1() {
    asm volatile("cp.async.wait_group 1;" ::: "memory");
}

// ---------------------------------------------------------------------------
// dtype detection: int64 indices < 2^31 -> all odd 32-bit words zero.
// ---------------------------------------------------------------------------
__global__ void detect_kernel(const int* __restrict__ w)
{
    int i = threadIdx.x;
    int nz = 0;
    #pragma unroll
    for (int k = 0; k < 4; k++) nz |= w[2 * (i * 4 + k) + 1];
    int any = __syncthreads_or(nz != 0);
    if (i == 0) g_idx_is64 = (any == 0) ? 1 : 0;
}

__global__ void __launch_bounds__(256)
relu_kernel(float4* __restrict__ out, int total4)
{
    int t = blockIdx.x * blockDim.x + threadIdx.x;
    if (t >= total4) return;
    float4 v = out[t];
    v.x = v.x > 0.f ? v.x : 0.f;
    v.y = v.y > 0.f ? v.y : 0.f;
    v.z = v.z > 0.f ? v.z : 0.f;
    v.w = v.w > 0.f ? v.w : 0.f;
    out[t] = v;
}

// ---------------------------------------------------------------------------
// Per-warp autonomous gemv + scatter. Warp-tile = 4 matrices; lane ->
// (e_loc = lane>>3, h = lane&7); thread owns rows 2h,2h+1. Weights staged
// via cp.async with XOR-swizzled smem slots; bias + indices + x[src]
// prefetched one tile ahead in registers. No block barriers in the loop.
//   is_edge=1: red.add.v2 to out[dst]  (accumulate onto self term)
//   is_edge=0: plain store (each output element written exactly once)
// ---------------------------------------------------------------------------
__global__ void __launch_bounds__(BLOCK_THREADS)
gemv_scatter_kernel(const float* __restrict__ x,
                    const void* __restrict__ edge_index,
                    const float* __restrict__ W,
                    const float* __restrict__ Bq,
                    float* __restrict__ out,
                    int count, int n_nodes, int is_edge)
{
    extern __shared__ char smem[];
    const int wid  = threadIdx.x >> 5;
    const int lane = threadIdx.x & 31;
    const int e_loc = lane >> 3;
    const int h     = lane & 7;
    char* wsm = smem + wid * WARP_SMEM;

    const int n_wtiles = (count + EPW - 1) / EPW;
    const int wslot    = blockIdx.x * BLOCK_WARPS + wid;
    const int wstride  = gridDim.x * BLOCK_WARPS;
    const int is64     = g_idx_is64;

    int n_local = (wslot < n_wtiles) ? (n_wtiles - wslot + wstride - 1) / wstride : 0;
    if (n_local == 0) return;

    auto issue_stage = [&](int buf, int i_local, bool real) {
        if (real) {
            long long ti = (long long)wslot + (long long)i_local * wstride;
            long long base_e = ti * EPW;
            int rem = (int)((count - base_e) < EPW ? (count - base_e) : EPW);
            const char* wsrc = (const char*)W + base_e * 1024;
            char* wd = wsm + buf * STAGE_BYTES;
            int units = rem * 64;
            #pragma unroll
            for (int u = 0; u < 8; u++) {
                int m = lane + u * 32;
                if (m < units) {
                    int e  = m >> 6;
                    int hh = (m >> 3) & 7;
                    int j  = m & 7;
                    cp16(smem_u32(wd + e * 1024 + hh * 128 + ((j ^ hh) << 4)),
                         wsrc + (size_t)m * 16);
                }
            }
        }
        cp_commit();
    };

    // meta (indices, bias, x gather) for warp-tile i_local, into caller regs
    auto load_meta = [&](int i_local, long long& src, long long& dst, bool& ok,
                         float2& bq,
                         float4& x0, float4& x1, float4& x2, float4& x3) {
        long long g = ((long long)wslot + (long long)i_local * wstride) * EPW + e_loc;
        ok = (g < count);
        src = g; dst = g;
        if (ok && is_edge) {
            if (is64) {
                const long long* p = (const long long*)edge_index;
                src = p[g];
                dst = p[(size_t)count + g];
            } else {
                const int* p = (const int*)edge_index;
                src = p[g];
                dst = p[(size_t)count + g];
            }
            ok = (src >= 0 && src < n_nodes && dst >= 0 && dst < n_nodes);
        }
        if (ok) {
            bq = *(const float2*)(Bq + g * D + h * 2);
            const float4* xp = (const float4*)(x + (size_t)src * D);
            x0 = xp[0]; x1 = xp[1]; x2 = xp[2]; x3 = xp[3];
        }
    };

    // prologue
    issue_stage(0, 0, true);
    issue_stage(1, 1, 1 < n_local);

    long long src_c, dst_c; bool ok_c;
    float2 bq_c;
    float4 c0, c1, c2, c3;
    load_meta(0, src_c, dst_c, ok_c, bq_c, c0, c1, c2, c3);

    for (int i = 0; i < n_local; i++) {
        // prefetch next tile's meta (overlaps with this tile's wait+compute)
        long long src_n, dst_n; bool ok_n;
        float2 bq_n;
        float4 n0, n1, n2, n3;
        if (i + 1 < n_local)
            load_meta(i + 1, src_n, dst_n, ok_n, bq_n, n0, n1, n2, n3);

        cp_wait1();          // stage i complete (per-warp group counting)
        __syncwarp();

        if (ok_c) {
            const float* wst = (const float*)(wsm + (i & 1) * STAGE_BYTES)
                             + e_loc * 256 + h * 32;
            float a0 = bq_c.x, a1 = bq_c.y;
            float4 w;
            w = *(const float4*)(wst + ((0 ^ h) << 2)); a0 += dot4(w, c0);
            w = *(const float4*)(wst + ((1 ^ h) << 2)); a0 += dot4(w, c1);
            w = *(const float4*)(wst + ((2 ^ h) << 2)); a0 += dot4(w, c2);
            w = *(const float4*)(wst + ((3 ^ h) << 2)); a0 += dot4(w, c3);
            w = *(const float4*)(wst + ((4 ^ h) << 2)); a1 += dot4(w, c0);
            w = *(const float4*)(wst + ((5 ^ h) << 2)); a1 += dot4(w, c1);
            w = *(const float4*)(wst + ((6 ^ h) << 2)); a1 += dot4(w, c2);
            w = *(const float4*)(wst + ((7 ^ h) << 2)); a1 += dot4(w, c3);
            if (is_edge)
                red_add_v2(out + (size_t)dst_c * D + h * 2, a0, a1);
            else
                *(float2*)(out + (size_t)dst_c * D + h * 2) = make_float2(a0, a1);
        }

        __syncwarp();
        // refill the consumed buffer with tile i+2 (issued after all reads)
        issue_stage(i & 1, i + 2, (i + 2) < n_local);

        src_c = src_n; dst_c = dst_n; ok_c = ok_n; bq_c = bq_n;
        c0 = n0; c1 = n1; c2 = n2; c3 = n3;
    }
}

extern "C" void kernel_launch(void* const* d_in, const int* in_sizes, int n_in,
                              void* d_out, int out_size)
{
    const float* x      = (const float*)d_in[0];
    const void*  eidx   = d_in[1];
    const float* w_edge = (const float*)d_in[2];
    const float* w_self = (const float*)d_in[3];
    const float* b_edge = (const float*)d_in[4];
    const float* b_self = (const float*)d_in[5];
    float*       out    = (float*)d_out;

    int n_nodes = in_sizes[0] / D;
    int n_edges = in_sizes[2] / (D * D);

    cudaFuncSetAttribute(gemv_scatter_kernel,
                         cudaFuncAttributeMaxDynamicSharedMemorySize, SMEM_TOTAL);

    // 0) index dtype detection
    detect_kernel<<<1, 256>>>((const int*)eidx);

    const int GRID = 1036;   // 7 CTAs/SM x 148 SMs (32KB smem/CTA)

    // 1) self term: plain stores, initializes every output element
    gemv_scatter_kernel<<<GRID, BLOCK_THREADS, SMEM_TOTAL>>>(
        x, eidx, w_self, b_self, out, n_nodes, n_nodes, 0);

    // 2) edge term: atomic accumulate
    gemv_scatter_kernel<<<GRID, BLOCK_THREADS, SMEM_TOTAL>>>(
        x, eidx, w_edge, b_edge, out, n_edges, n_nodes, 1);

    // 3) relu
    int total4 = (n_nodes * D) / 4;
    relu_kernel<<<(total4 + 255) / 256, 256>>>((float4*)out, total4);
}

// round 15
// speedup vs baseline: 1.1272x; 1.1272x over previous
#include <cuda_runtime.h>
#include <cstdint>

// SheafConvLayer:
//   out[n,:] = relu( W_self[n] @ x[n] + b_self[n]
//                    + sum_{e: dst[e]==n} ( W_edge[e] @ x[src[e]] + b_edge[e] ) )
// D = 16.
//
// Inputs (metadata order):
//   0: x           f32 [N,16]
//   1: edge_index  int [2,E]  (int32 or int64, runtime-detected)
//   2: weight_edge f32 [E,16,16]
//   3: weight_self f32 [N,16,16]
//   4: bias_edge   f32 [E,16]
//   5: bias_self   f32 [N,16]
// out: f32 [N,16]
//
// R11 config (measured best: 6.6TB/s, DRAM 83%): 256-thread blocks, GRID 444
// (3 CTAs/SM), per-warp autonomous 2-stage cp.async pipelines, 4 matrices
// per warp-tile, bias staged in smem, indices + x[src] prefetched one tile
// ahead in registers. R12's occupancy push (7 CTAs/SM) regressed -> reverted.
//
// R13/R14: self and edge terms merged into ONE kernel over a concatenated
// tile space (tiles [0, n_self_tiles) = self with src=dst=node, rest = edge).
// Both accumulate via red.add.v2 onto a zeroed output. Saves one launch
// boundary + pipeline prologue/epilogue; self traffic joins the same stream.
// (R13 bench was an infra failure - container died twice - resubmitted.)

#define D 16
#define EPW 4                       // matrices per warp-tile
#define WT_W_BYTES (EPW * 1024)     // 4 KB weights per stage
#define WT_B_BYTES (EPW * 64)       // 256 B bias per stage
#define STAGE_BYTES (WT_W_BYTES + WT_B_BYTES)   // 4352
#define NSTAGE 2
#define WARP_SMEM (NSTAGE * STAGE_BYTES)        // 8704
#define BLOCK_WARPS 8
#define BLOCK_THREADS (BLOCK_WARPS * 32)        // 256
#define SMEM_TOTAL (BLOCK_WARPS * WARP_SMEM)    // 69632

__device__ int g_idx_is64;

__device__ __forceinline__ float dot4(float4 a, float4 b) {
    return a.x * b.x + a.y * b.y + a.z * b.z + a.w * b.w;
}

__device__ __forceinline__ void red_add_v2(float* addr, float a, float b) {
    asm volatile("red.global.add.v2.f32 [%0], {%1, %2};"
                 :: "l"(addr), "f"(a), "f"(b) : "memory");
}

__device__ __forceinline__ uint32_t smem_u32(const void* p) {
    uint32_t a;
    asm("{ .reg .u64 t; cvta.to.shared.u64 t, %1; cvt.u32.u64 %0, t; }"
        : "=r"(a) : "l"(p));
    return a;
}

__device__ __forceinline__ void cp16(uint32_t dst, const void* src) {
    asm volatile("cp.async.cg.shared.global [%0], [%1], 16;"
                 :: "r"(dst), "l"(src) : "memory");
}

__device__ __forceinline__ void cp_commit() {
    asm volatile("cp.async.commit_group;" ::: "memory");
}

__device__ __forceinline__ void cp_wait1() {
    asm volatile("cp.async.wait_group 1;" ::: "memory");
}

// ---------------------------------------------------------------------------
// dtype detection: int64 indices < 2^31 -> all odd 32-bit words zero.
// ---------------------------------------------------------------------------
__global__ void detect_kernel(const int* __restrict__ w)
{
    int i = threadIdx.x;
    int nz = 0;
    #pragma unroll
    for (int k = 0; k < 4; k++) nz |= w[2 * (i * 4 + k) + 1];
    int any = __syncthreads_or(nz != 0);
    if (i == 0) g_idx_is64 = (any == 0) ? 1 : 0;
}

__global__ void __launch_bounds__(256)
zero_kernel(float4* __restrict__ out, int total4)
{
    int t = blockIdx.x * blockDim.x + threadIdx.x;
    if (t < total4) out[t] = make_float4(0.f, 0.f, 0.f, 0.f);
}

__global__ void __launch_bounds__(256)
relu_kernel(float4* __restrict__ out, int total4)
{
    int t = blockIdx.x * blockDim.x + threadIdx.x;
    if (t >= total4) return;
    float4 v = out[t];
    v.x = v.x > 0.f ? v.x : 0.f;
    v.y = v.y > 0.f ? v.y : 0.f;
    v.z = v.z > 0.f ? v.z : 0.f;
    v.w = v.w > 0.f ? v.w : 0.f;
    out[t] = v;
}

// ---------------------------------------------------------------------------
// Unified per-warp gemv + scatter-add over concatenated tile space.
// Warp-tile = 4 matrices; lane -> (e_loc = lane>>3, h = lane&7); thread owns
// rows 2h,2h+1. Weights+bias staged via cp.async with XOR-swizzled smem
// slots; indices + x[src] prefetched one tile ahead in registers. No block
// barriers in the mainloop. All contributions via red.add.v2 (out zeroed).
// ---------------------------------------------------------------------------
__global__ void __launch_bounds__(BLOCK_THREADS)
gemv_scatter_kernel(const float* __restrict__ x,
                    const void* __restrict__ edge_index,
                    const float* __restrict__ w_edge,
                    const float* __restrict__ w_self,
                    const float* __restrict__ b_edge,
                    const float* __restrict__ b_self,
                    float* __restrict__ out,
                    int n_nodes, int n_edges)
{
    extern __shared__ char smem[];
    const int wid  = threadIdx.x >> 5;
    const int lane = threadIdx.x & 31;
    const int e_loc = lane >> 3;
    const int h     = lane & 7;
    char* wsm = smem + wid * WARP_SMEM;

    const int n_self_tiles = (n_nodes + EPW - 1) / EPW;
    const int n_edge_tiles = (n_edges + EPW - 1) / EPW;
    const int n_wtiles = n_self_tiles + n_edge_tiles;

    const int wslot   = blockIdx.x * BLOCK_WARPS + wid;
    const int wstride = gridDim.x * BLOCK_WARPS;
    const int is64    = g_idx_is64;

    int n_local = (wslot < n_wtiles) ? (n_wtiles - wslot + wstride - 1) / wstride : 0;
    if (n_local == 0) return;

    auto issue_stage = [&](int buf, int i_local, bool real) {
        if (real) {
            int ti = wslot + i_local * wstride;
            const float* Wp; const float* Bp; long long base_e; int seg;
            if (ti < n_self_tiles) {
                Wp = w_self; Bp = b_self; base_e = (long long)ti * EPW; seg = n_nodes;
            } else {
                Wp = w_edge; Bp = b_edge;
                base_e = (long long)(ti - n_self_tiles) * EPW; seg = n_edges;
            }
            int rem = (int)((seg - base_e) < EPW ? (seg - base_e) : EPW);
            const char* wsrc = (const char*)Wp + base_e * 1024;
            char* wd = wsm + buf * STAGE_BYTES;
            int units = rem * 64;
            #pragma unroll
            for (int u = 0; u < 8; u++) {
                int m = lane + u * 32;
                if (m < units) {
                    int e  = m >> 6;
                    int hh = (m >> 3) & 7;
                    int j  = m & 7;
                    cp16(smem_u32(wd + e * 1024 + hh * 128 + ((j ^ hh) << 4)),
                         wsrc + (size_t)m * 16);
                }
            }
            const char* bsrc = (const char*)Bp + base_e * 64;
            if (lane < rem * 4)
                cp16(smem_u32(wd + WT_W_BYTES + lane * 16), bsrc + (size_t)lane * 16);
        }
        cp_commit();
    };

    // meta (indices + x gather) for warp-tile i_local, into caller regs
    auto load_meta = [&](int i_local, long long& src, long long& dst, bool& ok,
                         float4& x0, float4& x1, float4& x2, float4& x3) {
        int ti = wslot + i_local * wstride;
        if (ti < n_self_tiles) {
            long long g = (long long)ti * EPW + e_loc;
            ok = (g < n_nodes);
            src = g; dst = g;
        } else {
            long long g = (long long)(ti - n_self_tiles) * EPW + e_loc;
            ok = (g < n_edges);
            src = 0; dst = 0;
            if (ok) {
                if (is64) {
                    const long long* p = (const long long*)edge_index;
                    src = p[g];
                    dst = p[(size_t)n_edges + g];
                } else {
                    const int* p = (const int*)edge_index;
                    src = p[g];
                    dst = p[(size_t)n_edges + g];
                }
                ok = (src >= 0 && src < n_nodes && dst >= 0 && dst < n_nodes);
            }
        }
        if (ok) {
            const float4* xp = (const float4*)(x + (size_t)src * D);
            x0 = xp[0]; x1 = xp[1]; x2 = xp[2]; x3 = xp[3];
        }
    };

    // prologue
    issue_stage(0, 0, true);
    issue_stage(1, 1, 1 < n_local);

    long long src_c, dst_c; bool ok_c;
    float4 c0, c1, c2, c3;
    load_meta(0, src_c, dst_c, ok_c, c0, c1, c2, c3);

    for (int i = 0; i < n_local; i++) {
        // prefetch next tile's meta (overlaps this tile's wait+compute)
        long long src_n, dst_n; bool ok_n;
        float4 n0, n1, n2, n3;
        if (i + 1 < n_local)
            load_meta(i + 1, src_n, dst_n, ok_n, n0, n1, n2, n3);

        cp_wait1();          // stage i complete (per-warp group counting)
        __syncwarp();

        if (ok_c) {
            const float* wst = (const float*)(wsm + (i & 1) * STAGE_BYTES)
                             + e_loc * 256 + h * 32;
            float2 b2 = *(const float2*)((const float*)(wsm + (i & 1) * STAGE_BYTES + WT_W_BYTES)
                                         + e_loc * 16 + h * 2);
            float a0 = b2.x, a1 = b2.y;
            float4 w;
            w = *(const float4*)(wst + ((0 ^ h) << 2)); a0 += dot4(w, c0);
            w = *(const float4*)(wst + ((1 ^ h) << 2)); a0 += dot4(w, c1);
            w = *(const float4*)(wst + ((2 ^ h) << 2)); a0 += dot4(w, c2);
            w = *(const float4*)(wst + ((3 ^ h) << 2)); a0 += dot4(w, c3);
            w = *(const float4*)(wst + ((4 ^ h) << 2)); a1 += dot4(w, c0);
            w = *(const float4*)(wst + ((5 ^ h) << 2)); a1 += dot4(w, c1);
            w = *(const float4*)(wst + ((6 ^ h) << 2)); a1 += dot4(w, c2);
            w = *(const float4*)(wst + ((7 ^ h) << 2)); a1 += dot4(w, c3);
            red_add_v2(out + (size_t)dst_c * D + h * 2, a0, a1);
        }

        __syncwarp();
        // refill the consumed buffer with tile i+2 (issued after all reads)
        issue_stage(i & 1, i + 2, (i + 2) < n_local);

        src_c = src_n; dst_c = dst_n; ok_c = ok_n;
        c0 = n0; c1 = n1; c2 = n2; c3 = n3;
    }
}

extern "C" void kernel_launch(void* const* d_in, const int* in_sizes, int n_in,
                              void* d_out, int out_size)
{
    const float* x      = (const float*)d_in[0];
    const void*  eidx   = d_in[1];
    const float* w_edge = (const float*)d_in[2];
    const float* w_self = (const float*)d_in[3];
    const float* b_edge = (const float*)d_in[4];
    const float* b_self = (const float*)d_in[5];
    float*       out    = (float*)d_out;

    int n_nodes = in_sizes[0] / D;
    int n_edges = in_sizes[2] / (D * D);

    cudaFuncSetAttribute(gemv_scatter_kernel,
                         cudaFuncAttributeMaxDynamicSharedMemorySize, SMEM_TOTAL);

    // 0) index dtype detection
    detect_kernel<<<1, 256>>>((const int*)eidx);

    // 1) zero output (all contributions accumulate atomically)
    int total4 = (n_nodes * D) / 4;
    zero_kernel<<<(total4 + 255) / 256, 256>>>((float4*)out, total4);

    // 2) self + edge terms, single launch over concatenated tile space
    const int GRID = 444;   // 3 CTAs/SM x 148 SMs (68KB smem/CTA)
    gemv_scatter_kernel<<<GRID, BLOCK_THREADS, SMEM_TOTAL>>>(
        x, eidx, w_edge, w_self, b_edge, b_self, out, n_nodes, n_edges);

    // 3) relu
    relu_kernel<<<(total4 + 255) / 256, 256>>>((float4*)out, total4);
}

// round 17
// speedup vs baseline: 1.1387x; 1.0101x over previous
#include <cuda_runtime.h>
#include <cstdint>

// SheafConvLayer:
//   out[n,:] = relu( W_self[n] @ x[n] + b_self[n]
//                    + sum_{e: dst[e]==n} ( W_edge[e] @ x[src[e]] + b_edge[e] ) )
// D = 16.
//
// Inputs (metadata order):
//   0: x           f32 [N,16]
//   1: edge_index  int [2,E]  (int32 or int64, detected inline per-warp)
//   2: weight_edge f32 [E,16,16]
//   3: weight_self f32 [N,16,16]
//   4: bias_edge   f32 [E,16]
//   5: bias_self   f32 [N,16]
// out: f32 [N,16]
//
// Measured-best core (R15: 166.0us, DRAM 83%, 6.6TB/s): 256-thread blocks,
// GRID 444 (3 CTAs/SM), per-warp autonomous 2-stage cp.async pipelines,
// 4 matrices/warp-tile, self+edge merged in one concatenated tile space,
// all contributions red.add.v2 onto zeroed output.
// R16: detect_kernel launch removed (inline per-warp dtype check, one cached
// 128B line); relu does 4 float4/thread to cut launch ramp.

#define D 16
#define EPW 4                       // matrices per warp-tile
#define WT_W_BYTES (EPW * 1024)     // 4 KB weights per stage
#define WT_B_BYTES (EPW * 64)       // 256 B bias per stage
#define STAGE_BYTES (WT_W_BYTES + WT_B_BYTES)   // 4352
#define NSTAGE 2
#define WARP_SMEM (NSTAGE * STAGE_BYTES)        // 8704
#define BLOCK_WARPS 8
#define BLOCK_THREADS (BLOCK_WARPS * 32)        // 256
#define SMEM_TOTAL (BLOCK_WARPS * WARP_SMEM)    // 69632

__device__ __forceinline__ float dot4(float4 a, float4 b) {
    return a.x * b.x + a.y * b.y + a.z * b.z + a.w * b.w;
}

__device__ __forceinline__ void red_add_v2(float* addr, float a, float b) {
    asm volatile("red.global.add.v2.f32 [%0], {%1, %2};"
                 :: "l"(addr), "f"(a), "f"(b) : "memory");
}

__device__ __forceinline__ uint32_t smem_u32(const void* p) {
    uint32_t a;
    asm("{ .reg .u64 t; cvta.to.shared.u64 t, %1; cvt.u32.u64 %0, t; }"
        : "=r"(a) : "l"(p));
    return a;
}

__device__ __forceinline__ void cp16(uint32_t dst, const void* src) {
    asm volatile("cp.async.cg.shared.global [%0], [%1], 16;"
                 :: "r"(dst), "l"(src) : "memory");
}

__device__ __forceinline__ void cp_commit() {
    asm volatile("cp.async.commit_group;" ::: "memory");
}

__device__ __forceinline__ void cp_wait1() {
    asm volatile("cp.async.wait_group 1;" ::: "memory");
}

__global__ void __launch_bounds__(256)
zero_kernel(float4* __restrict__ out, int total4)
{
    int t = blockIdx.x * blockDim.x + threadIdx.x;
    if (t < total4) out[t] = make_float4(0.f, 0.f, 0.f, 0.f);
}

// 4 float4s per thread (consecutive-coalesced via stride) to cut launch ramp.
__global__ void __launch_bounds__(256)
relu_kernel(float4* __restrict__ out, int total4)
{
    int base = blockIdx.x * (blockDim.x * 4) + threadIdx.x;
    #pragma unroll
    for (int k = 0; k < 4; k++) {
        int t = base + k * 256;
        if (t < total4) {
            float4 v = out[t];
            v.x = v.x > 0.f ? v.x : 0.f;
            v.y = v.y > 0.f ? v.y : 0.f;
            v.z = v.z > 0.f ? v.z : 0.f;
            v.w = v.w > 0.f ? v.w : 0.f;
            out[t] = v;
        }
    }
}

// ---------------------------------------------------------------------------
// Unified per-warp gemv + scatter-add over concatenated tile space.
// Warp-tile = 4 matrices; lane -> (e_loc = lane>>3, h = lane&7); thread owns
// rows 2h,2h+1. Weights+bias staged via cp.async with XOR-swizzled smem
// slots; indices + x[src] prefetched one tile ahead in registers. No block
// barriers in the mainloop. All contributions via red.add.v2 (out zeroed).
// ---------------------------------------------------------------------------
__global__ void __launch_bounds__(BLOCK_THREADS)
gemv_scatter_kernel(const float* __restrict__ x,
                    const void* __restrict__ edge_index,
                    const float* __restrict__ w_edge,
                    const float* __restrict__ w_self,
                    const float* __restrict__ b_edge,
                    const float* __restrict__ b_self,
                    float* __restrict__ out,
                    int n_nodes, int n_edges)
{
    extern __shared__ char smem[];
    const int wid  = threadIdx.x >> 5;
    const int lane = threadIdx.x & 31;
    const int e_loc = lane >> 3;
    const int h     = lane & 7;
    char* wsm = smem + wid * WARP_SMEM;

    // Inline dtype detection: int64 indices < 2^31 -> odd 32-bit words of the
    // first 16 pairs are all zero; int32 data has random node ids there
    // (P[16 indices all ==0] ~ 1e-80). One L1-cached 128B line per warp.
    int hiw = (lane < 16) ? ((const int*)edge_index)[2 * lane + 1] : 0;
    const int is64 = !__any_sync(0xffffffffu, hiw != 0);

    const int n_self_tiles = (n_nodes + EPW - 1) / EPW;
    const int n_edge_tiles = (n_edges + EPW - 1) / EPW;
    const int n_wtiles = n_self_tiles + n_edge_tiles;

    const int wslot   = blockIdx.x * BLOCK_WARPS + wid;
    const int wstride = gridDim.x * BLOCK_WARPS;

    int n_local = (wslot < n_wtiles) ? (n_wtiles - wslot + wstride - 1) / wstride : 0;
    if (n_local == 0) return;

    auto issue_stage = [&](int buf, int i_local, bool real) {
        if (real) {
            int ti = wslot + i_local * wstride;
            const float* Wp; const float* Bp; long long base_e; int seg;
            if (ti < n_self_tiles) {
                Wp = w_self; Bp = b_self; base_e = (long long)ti * EPW; seg = n_nodes;
            } else {
                Wp = w_edge; Bp = b_edge;
                base_e = (long long)(ti - n_self_tiles) * EPW; seg = n_edges;
            }
            int rem = (int)((seg - base_e) < EPW ? (seg - base_e) : EPW);
            const char* wsrc = (const char*)Wp + base_e * 1024;
            char* wd = wsm + buf * STAGE_BYTES;
            int units = rem * 64;
            #pragma unroll
            for (int u = 0; u < 8; u++) {
                int m = lane + u * 32;
                if (m < units) {
                    int e  = m >> 6;
                    int hh = (m >> 3) & 7;
                    int j  = m & 7;
                    cp16(smem_u32(wd + e * 1024 + hh * 128 + ((j ^ hh) << 4)),
                         wsrc + (size_t)m * 16);
                }
            }
            const char* bsrc = (const char*)Bp + base_e * 64;
            if (lane < rem * 4)
                cp16(smem_u32(wd + WT_W_BYTES + lane * 16), bsrc + (size_t)lane * 16);
        }
        cp_commit();
    };

    // meta (indices + x gather) for warp-tile i_local, into caller regs
    auto load_meta = [&](int i_local, long long& src, long long& dst, bool& ok,
                         float4& x0, float4& x1, float4& x2, float4& x3) {
        int ti = wslot + i_local * wstride;
        if (ti < n_self_tiles) {
            long long g = (long long)ti * EPW + e_loc;
            ok = (g < n_nodes);
            src = g; dst = g;
        } else {
            long long g = (long long)(ti - n_self_tiles) * EPW + e_loc;
            ok = (g < n_edges);
            src = 0; dst = 0;
            if (ok) {
                if (is64) {
                    const long long* p = (const long long*)edge_index;
                    src = p[g];
                    dst = p[(size_t)n_edges + g];
                } else {
                    const int* p = (const int*)edge_index;
                    src = p[g];
                    dst = p[(size_t)n_edges + g];
                }
                ok = (src >= 0 && src < n_nodes && dst >= 0 && dst < n_nodes);
            }
        }
        if (ok) {
            const float4* xp = (const float4*)(x + (size_t)src * D);
            x0 = xp[0]; x1 = xp[1]; x2 = xp[2]; x3 = xp[3];
        }
    };

    // prologue
    issue_stage(0, 0, true);
    issue_stage(1, 1, 1 < n_local);

    long long src_c, dst_c; bool ok_c;
    float4 c0, c1, c2, c3;
    load_meta(0, src_c, dst_c, ok_c, c0, c1, c2, c3);

    for (int i = 0; i < n_local; i++) {
        // prefetch next tile's meta (overlaps this tile's wait+compute)
        long long src_n, dst_n; bool ok_n;
        float4 n0, n1, n2, n3;
        if (i + 1 < n_local)
            load_meta(i + 1, src_n, dst_n, ok_n, n0, n1, n2, n3);

        cp_wait1();          // stage i complete (per-warp group counting)
        __syncwarp();

        if (ok_c) {
            const float* wst = (const float*)(wsm + (i & 1) * STAGE_BYTES)
                             + e_loc * 256 + h * 32;
            float2 b2 = *(const float2*)((const float*)(wsm + (i & 1) * STAGE_BYTES + WT_W_BYTES)
                                         + e_loc * 16 + h * 2);
            float a0 = b2.x, a1 = b2.y;
            float4 w;
            w = *(const float4*)(wst + ((0 ^ h) << 2)); a0 += dot4(w, c0);
            w = *(const float4*)(wst + ((1 ^ h) << 2)); a0 += dot4(w, c1);
            w = *(const float4*)(wst + ((2 ^ h) << 2)); a0 += dot4(w, c2);
            w = *(const float4*)(wst + ((3 ^ h) << 2)); a0 += dot4(w, c3);
            w = *(const float4*)(wst + ((4 ^ h) << 2)); a1 += dot4(w, c0);
            w = *(const float4*)(wst + ((5 ^ h) << 2)); a1 += dot4(w, c1);
            w = *(const float4*)(wst + ((6 ^ h) << 2)); a1 += dot4(w, c2);
            w = *(const float4*)(wst + ((7 ^ h) << 2)); a1 += dot4(w, c3);
            red_add_v2(out + (size_t)dst_c * D + h * 2, a0, a1);
        }

        __syncwarp();
        // refill the consumed buffer with tile i+2 (issued after all reads)
        issue_stage(i & 1, i + 2, (i + 2) < n_local);

        src_c = src_n; dst_c = dst_n; ok_c = ok_n;
        c0 = n0; c1 = n1; c2 = n2; c3 = n3;
    }
}

extern "C" void kernel_launch(void* const* d_in, const int* in_sizes, int n_in,
                              void* d_out, int out_size)
{
    const float* x      = (const float*)d_in[0];
    const void*  eidx   = d_in[1];
    const float* w_edge = (const float*)d_in[2];
    const float* w_self = (const float*)d_in[3];
    const float* b_edge = (const float*)d_in[4];
    const float* b_self = (const float*)d_in[5];
    float*       out    = (float*)d_out;

    int n_nodes = in_sizes[0] / D;
    int n_edges = in_sizes[2] / (D * D);

    cudaFuncSetAttribute(gemv_scatter_kernel,
                         cudaFuncAttributeMaxDynamicSharedMemorySize, SMEM_TOTAL);

    // 1) zero output (all contributions accumulate atomically)
    int total4 = (n_nodes * D) / 4;
    zero_kernel<<<(total4 + 255) / 256, 256>>>((float4*)out, total4);

    // 2) self + edge terms, single launch over concatenated tile space
    const int GRID = 444;   // 3 CTAs/SM x 148 SMs (68KB smem/CTA)
    gemv_scatter_kernel<<<GRID, BLOCK_THREADS, SMEM_TOTAL>>>(
        x, eidx, w_edge, w_self, b_edge, b_self, out, n_nodes, n_edges);

    // 3) relu (4 float4/thread)
    relu_kernel<<<(total4 + 1023) / 1024, 256>>>((float4*)out, total4);
}